// round 8
// baseline (speedup 1.0000x reference)
#include <cuda_runtime.h>
#include <math.h>

#define B_SAMPLES 128
#define T_LEN     8192
#define C_CLASSES 64
#define OUT_LEN   8

#define THREADS   1024
#define N_WARPS   32
#define EPT       (T_LEN / THREADS)       // 8 contiguous elems per thread
#define Q_TOTAL   128                     // position-pairs per warp (8192 / (32*2))
#define L2E       1.4426950408889634f

__device__ __forceinline__ float ex2_approx(float t) {
    float r;
    asm("ex2.approx.ftz.f32 %0, %1;" : "=f"(r) : "f"(t));
    return r;
}

// ---------------------------------------------------------------------------
// Fused kernel: one CTA per sample.
// Phase 1: 16 lanes/position, one fully-contiguous LDG.128 per lane per pass
//   (4 full lines/warp-load => minimal L1 wavefronts), 4-pass unroll for MLP.
// Phase 2: RLE + top-8 by voted confidence (exact), smem/registers.
// ---------------------------------------------------------------------------
__global__ __launch_bounds__(THREADS, 1)
void fused_kernel(const float* __restrict__ x, float* __restrict__ out) {
    __shared__ float         sconf[T_LEN];          // 32 KB
    __shared__ unsigned char spred[T_LEN];          //  8 KB
    __shared__ float candv[OUT_LEN * 32];           // [round][warp]
    __shared__ int   candi[OUT_LEN * 32];
    __shared__ float outv[OUT_LEN];
    __shared__ int   outi[OUT_LEN];

    const int b    = blockIdx.x;
    const int tid  = threadIdx.x;
    const int lane = tid & 31;
    const int wid  = tid >> 5;

    const float4* __restrict__ xb4 =
        (const float4*)(x + (size_t)b * T_LEN * C_CLASSES);

    // ================= Phase 1: stream 2MB, compute conf/pred =================
    // Pass q (0..127): warp handles positions 2*(q*32+wid), +1.
    // Lane covers classes (lane&15)*4 .. +3 of position pairbase + (lane>>4).
    for (int i = 0; i < Q_TOTAL / 4; i++) {
        float4 F[4];
        #pragma unroll
        for (int j = 0; j < 4; j++) {
            int q = i * 4 + j;
            F[j] = xb4[((q * 32 + wid) * 32) + lane];   // warp: 512B contiguous
        }
        #pragma unroll
        for (int j = 0; j < 4; j++) {
            int q   = i * 4 + j;
            int pos = (q * 32 + wid) * 2 + (lane >> 4);
            float4 f = F[j];

            // Local max (values only) + first-occurrence argmax within 4
            float m4 = fmaxf(fmaxf(f.x, f.y), fmaxf(f.z, f.w));
            int am = (f.x >= m4) ? 0 : (f.y >= m4) ? 1 : (f.z >= m4) ? 2 : 3;

            // Group max over the 16 lanes of this position
            float m = m4;
            #pragma unroll
            for (int d = 1; d < 16; d <<= 1)
                m = fmaxf(m, __shfl_xor_sync(0xFFFFFFFFu, m, d));

            // Argmax: lowest lane holding the max (lane order == class order)
            unsigned bal = __ballot_sync(0xFFFFFFFFu, m4 == m);
            int g = lane & 16;                       // group base: 0 or 16
            unsigned half = (bal >> g) & 0xFFFFu;
            int src = g + __ffs(half) - 1;
            int cls = ((lane & 15) << 2) + am;
            int wcls = __shfl_sync(0xFFFFFFFFu, cls, src);

            // exp2-based softmax denominator: FFMA + MUFU.EX2 per element
            float mb = m * L2E;
            float s = ex2_approx(fmaf(f.x, L2E, -mb))
                    + ex2_approx(fmaf(f.y, L2E, -mb))
                    + ex2_approx(fmaf(f.z, L2E, -mb))
                    + ex2_approx(fmaf(f.w, L2E, -mb));
            #pragma unroll
            for (int d = 1; d < 16; d <<= 1)
                s += __shfl_xor_sync(0xFFFFFFFFu, s, d);

            if ((lane & 15) == 0) {
                sconf[pos] = __fdividef(1.0f, s);
                spred[pos] = (unsigned char)wcls;
            }
        }
    }
    __syncthreads();

    // ================= Phase 2: RLE + top-8 (smem/registers) =================
    const int t0 = tid * EPT;

    uint2 pv2 = ((const uint2*)spred)[tid];
    unsigned char pb[EPT];
    pb[0] = (unsigned char)(pv2.x);        pb[1] = (unsigned char)(pv2.x >> 8);
    pb[2] = (unsigned char)(pv2.x >> 16);  pb[3] = (unsigned char)(pv2.x >> 24);
    pb[4] = (unsigned char)(pv2.y);        pb[5] = (unsigned char)(pv2.y >> 8);
    pb[6] = (unsigned char)(pv2.y >> 16);  pb[7] = (unsigned char)(pv2.y >> 24);

    float4 c0 = ((const float4*)sconf)[tid * 2];
    float4 c1 = ((const float4*)sconf)[tid * 2 + 1];
    float cf[EPT] = {c0.x, c0.y, c0.z, c0.w, c1.x, c1.y, c1.z, c1.w};

    unsigned char prev = (tid == 0) ? (unsigned char)(pb[0] ^ 1) : spred[t0 - 1];

    float lv[EPT];
    #pragma unroll
    for (int j = 0; j < EPT; j++) {
        unsigned char cur = pb[j];
        unsigned char before = (j == 0) ? prev : pb[j - 1];
        bool start = (t0 + j == 0) || (cur != before);
        float v = -INFINITY;
        if (start) {
            int cnt = 1;
            int jj = j + 1;
            while (jj < EPT && pb[jj] == cur) { cnt++; jj++; }   // reg scan
            if (jj == EPT) {                                      // rare spill
                int e = t0 + EPT;
                while (e < T_LEN && spred[e] == cur) { cnt++; e++; }
            }
            v = cf[j] * (float)cnt;
        }
        lv[j] = v;
    }

    // ---- Phase A: per-warp top-8 (no barriers) ----
    #pragma unroll
    for (int k = 0; k < OUT_LEN; k++) {
        float bv = lv[0];
        int   bj = 0;
        #pragma unroll
        for (int j = 1; j < EPT; j++)
            if (lv[j] > bv) { bv = lv[j]; bj = j; }   // j asc = index asc
        int bi = t0 + bj;

        #pragma unroll
        for (int d = 16; d > 0; d >>= 1) {
            float ov = __shfl_xor_sync(0xFFFFFFFFu, bv, d);
            int   oi = __shfl_xor_sync(0xFFFFFFFFu, bi, d);
            if (ov > bv || (ov == bv && oi < bi)) { bv = ov; bi = oi; }
        }
        if (lane == 0) {
            candv[k * 32 + wid] = bv;
            candi[k * 32 + wid] = bi;
        }
        if ((bi >> 3) == tid)              // owner invalidates
            lv[bi & (EPT - 1)] = -INFINITY;
    }
    __syncthreads();

    // ---- Phase B: warp 0 merges 32x8 candidates ----
    if (wid == 0) {
        float cv[OUT_LEN];
        int   ci[OUT_LEN];
        #pragma unroll
        for (int r = 0; r < OUT_LEN; r++) {
            cv[r] = candv[r * 32 + lane];
            ci[r] = candi[r * 32 + lane];
        }
        #pragma unroll
        for (int k = 0; k < OUT_LEN; k++) {
            // Per-lane candidates are value-desc / index-asc on ties, so a
            // strict > scan keeps the lowest-index tie, matching lax.top_k.
            float bv = cv[0];
            int   bi = ci[0], br = 0;
            #pragma unroll
            for (int r = 1; r < OUT_LEN; r++)
                if (cv[r] > bv) { bv = cv[r]; bi = ci[r]; br = r; }
            float mv = bv; int mi = bi;
            #pragma unroll
            for (int d = 16; d > 0; d >>= 1) {
                float ov = __shfl_xor_sync(0xFFFFFFFFu, mv, d);
                int   oi = __shfl_xor_sync(0xFFFFFFFFu, mi, d);
                if (ov > mv || (ov == mv && oi < mi)) { mv = ov; mi = oi; }
            }
            if (lane == 0) { outv[k] = mv; outi[k] = mi; }
            if (bi == mi) cv[br] = -INFINITY;   // unique index -> one owner
        }
    }
    __syncthreads();

    if (tid < OUT_LEN) {
        float v = outv[tid];
        int   i = outi[tid];
        float o = 0.0f;                               // pad-with-zero path
        if (isfinite(v)) o = (float)spred[i];
        out[(size_t)b * OUT_LEN + tid] = o;
    }
}

// ---------------------------------------------------------------------------
extern "C" void kernel_launch(void* const* d_in, const int* in_sizes, int n_in,
                              void* d_out, int out_size) {
    const float* x = (const float*)d_in[0];
    float* out = (float*)d_out;

    fused_kernel<<<B_SAMPLES, THREADS>>>(x, out);
}

// round 10
// speedup vs baseline: 1.1620x; 1.1620x over previous
#include <cuda_runtime.h>
#include <math.h>

#define B_SAMPLES 128
#define T_LEN     8192
#define C_CLASSES 64
#define OUT_LEN   8

#define K1_THREADS 256
#define POS_PER_CTA (K1_THREADS / 4)            // 4 threads per position
#define K2_THREADS 1024
#define EPT 8                                    // contiguous elems per thread
#define L2E 1.4426950408889634f

// Scratch (allocation-free __device__ globals)
__device__ __align__(16) float         g_conf[B_SAMPLES * T_LEN];
__device__ __align__(16) unsigned char g_pred[B_SAMPLES * T_LEN];

__device__ __forceinline__ float ex2_approx(float t) {
    float r;
    asm("ex2.approx.ftz.f32 %0, %1;" : "=f"(r) : "f"(t));
    return r;
}

// L2 evict-last cache policy (createpolicy + cache_hint form, valid on sm_103)
__device__ __forceinline__ unsigned long long mk_evict_last_policy() {
    unsigned long long pol;
    asm("createpolicy.fractional.L2::evict_last.b64 %0, 1.0;" : "=l"(pol));
    return pol;
}
__device__ __forceinline__ void st_el_f32(float* p, float v, unsigned long long pol) {
    asm volatile("st.global.L2::cache_hint.f32 [%0], %1, %2;"
                 :: "l"(p), "f"(v), "l"(pol) : "memory");
}
__device__ __forceinline__ void st_el_u8(unsigned char* p, unsigned short v,
                                         unsigned long long pol) {
    asm volatile("st.global.L2::cache_hint.u8 [%0], %1, %2;"
                 :: "l"(p), "h"(v), "l"(pol) : "memory");
}

// ---------------------------------------------------------------------------
// K1: softmax confidence (max prob) + argmax, 4 threads per position.
// Full-chip grid (16384 CTAs x 256 thr). Plain x loads; evict-last results
// (5MB working set pinned in L2 under the 256MB stream for K2).
// ---------------------------------------------------------------------------
__global__ __launch_bounds__(K1_THREADS)
void softmax_conf_kernel(const float* __restrict__ x) {
    const int tid  = threadIdx.x;
    const int part = tid & 3;            // which 16-class chunk
    const size_t pos = (size_t)blockIdx.x * POS_PER_CTA + (tid >> 2);

    const float4* __restrict__ p =
        (const float4*)(x + pos * C_CLASSES + part * 16);
    float4 v0 = p[0], v1 = p[1], v2 = p[2], v3 = p[3];

    float r[16] = {v0.x, v0.y, v0.z, v0.w, v1.x, v1.y, v1.z, v1.w,
                   v2.x, v2.y, v2.z, v2.w, v3.x, v3.y, v3.z, v3.w};

    // Value max via FMNMX chain
    float m = r[0];
    #pragma unroll
    for (int c = 1; c < 16; c++) m = fmaxf(m, r[c]);

    // First-occurrence argmax: descending >= (r[c] <= m, so >= means ==)
    int am = 0;
    #pragma unroll
    for (int c = 15; c >= 0; c--)
        if (r[c] >= m) am = c;
    int amg = part * 16 + am;

    // Combine across the 4 cooperating lanes (xor 1,2 stays in group)
    #pragma unroll
    for (int d = 1; d < 4; d <<= 1) {
        float om = __shfl_xor_sync(0xFFFFFFFFu, m,   d);
        int   oa = __shfl_xor_sync(0xFFFFFFFFu, amg, d);
        if (om > m || (om == m && oa < amg)) { m = om; amg = oa; }
    }

    // exp2-based softmax denominator: FFMA + MUFU.EX2 per element
    float mb = m * L2E;
    float s = 0.0f;
    #pragma unroll
    for (int c = 0; c < 16; c++)
        s += ex2_approx(fmaf(r[c], L2E, -mb));
    #pragma unroll
    for (int d = 1; d < 4; d <<= 1)
        s += __shfl_xor_sync(0xFFFFFFFFu, s, d);

    if (part == 0) {
        unsigned long long pol = mk_evict_last_policy();
        st_el_f32(&g_conf[pos], __fdividef(1.0f, s), pol);
        st_el_u8(&g_pred[pos], (unsigned short)amg, pol);
    }
}

// ---------------------------------------------------------------------------
// K2: per-sample RLE + top-8. One CTA (1024 thr) per sample.
// Front-batched unconditional loads (L2 hits thanks to evict_last stores).
// ---------------------------------------------------------------------------
__global__ __launch_bounds__(K2_THREADS)
void topk_kernel(float* __restrict__ out) {
    __shared__ unsigned char spred[T_LEN];           // 8 KB
    __shared__ float candv[OUT_LEN * 32];            // [round][warp]
    __shared__ int   candi[OUT_LEN * 32];
    __shared__ float outv[OUT_LEN];
    __shared__ int   outi[OUT_LEN];

    const int b    = blockIdx.x;
    const int tid  = threadIdx.x;
    const int lane = tid & 31;
    const int wid  = tid >> 5;
    const size_t off = (size_t)b * T_LEN;
    const int t0 = tid * EPT;

    // ---- Front-batched, unconditional loads ----
    uint2  pv2 = ((const uint2*)(g_pred + off))[tid];
    float4 c0  = ((const float4*)(g_conf + off))[tid * 2];
    float4 c1  = ((const float4*)(g_conf + off))[tid * 2 + 1];

    ((uint2*)spred)[tid] = pv2;
    __syncthreads();

    unsigned char pb[EPT];
    pb[0] = (unsigned char)(pv2.x);        pb[1] = (unsigned char)(pv2.x >> 8);
    pb[2] = (unsigned char)(pv2.x >> 16);  pb[3] = (unsigned char)(pv2.x >> 24);
    pb[4] = (unsigned char)(pv2.y);        pb[5] = (unsigned char)(pv2.y >> 8);
    pb[6] = (unsigned char)(pv2.y >> 16);  pb[7] = (unsigned char)(pv2.y >> 24);
    float cf[EPT] = {c0.x, c0.y, c0.z, c0.w, c1.x, c1.y, c1.z, c1.w};

    unsigned char prev = (tid == 0) ? (unsigned char)(pb[0] ^ 1) : spred[t0 - 1];

    float lv[EPT];
    #pragma unroll
    for (int j = 0; j < EPT; j++) {
        unsigned char cur = pb[j];
        unsigned char before = (j == 0) ? prev : pb[j - 1];
        bool start = (t0 + j == 0) || (cur != before);
        float v = -INFINITY;
        if (start) {
            int cnt = 1;
            int jj = j + 1;
            while (jj < EPT && pb[jj] == cur) { cnt++; jj++; }   // reg scan
            if (jj == EPT) {                                      // rare spill
                int e = t0 + EPT;
                while (e < T_LEN && spred[e] == cur) { cnt++; e++; }
            }
            v = cf[j] * (float)cnt;
        }
        lv[j] = v;
    }

    // ---- Phase A: per-warp top-8 (no barriers) ----
    #pragma unroll
    for (int k = 0; k < OUT_LEN; k++) {
        float bv = lv[0];
        int   bj = 0;
        #pragma unroll
        for (int j = 1; j < EPT; j++)
            if (lv[j] > bv) { bv = lv[j]; bj = j; }   // j asc = index asc
        int bi = t0 + bj;

        #pragma unroll
        for (int d = 16; d > 0; d >>= 1) {
            float ov = __shfl_xor_sync(0xFFFFFFFFu, bv, d);
            int   oi = __shfl_xor_sync(0xFFFFFFFFu, bi, d);
            if (ov > bv || (ov == bv && oi < bi)) { bv = ov; bi = oi; }
        }
        if (lane == 0) {
            candv[k * 32 + wid] = bv;
            candi[k * 32 + wid] = bi;
        }
        if ((bi >> 3) == tid)              // owner invalidates
            lv[bi & (EPT - 1)] = -INFINITY;
    }
    __syncthreads();

    // ---- Phase B: warp 0 merges 32x8 candidates ----
    if (wid == 0) {
        float cv[OUT_LEN];
        int   ci[OUT_LEN];
        #pragma unroll
        for (int r = 0; r < OUT_LEN; r++) {
            cv[r] = candv[r * 32 + lane];
            ci[r] = candi[r * 32 + lane];
        }
        #pragma unroll
        for (int k = 0; k < OUT_LEN; k++) {
            // Per-lane candidates are value-desc / index-asc on ties, so a
            // strict > scan keeps the lowest-index tie, matching lax.top_k.
            float bv = cv[0];
            int   bi = ci[0], br = 0;
            #pragma unroll
            for (int r = 1; r < OUT_LEN; r++)
                if (cv[r] > bv) { bv = cv[r]; bi = ci[r]; br = r; }
            float mv = bv; int mi = bi;
            #pragma unroll
            for (int d = 16; d > 0; d >>= 1) {
                float ov = __shfl_xor_sync(0xFFFFFFFFu, mv, d);
                int   oi = __shfl_xor_sync(0xFFFFFFFFu, mi, d);
                if (ov > mv || (ov == mv && oi < mi)) { mv = ov; mi = oi; }
            }
            if (lane == 0) { outv[k] = mv; outi[k] = mi; }
            if (bi == mi) cv[br] = -INFINITY;   // unique index -> one owner
        }
    }
    __syncthreads();

    if (tid < OUT_LEN) {
        float v = outv[tid];
        int   i = outi[tid];
        float o = 0.0f;                               // pad-with-zero path
        if (isfinite(v)) o = (float)spred[i];
        out[(size_t)b * OUT_LEN + tid] = o;
    }
}

// ---------------------------------------------------------------------------
extern "C" void kernel_launch(void* const* d_in, const int* in_sizes, int n_in,
                              void* d_out, int out_size) {
    const float* x = (const float*)d_in[0];
    float* out = (float*)d_out;

    const int n_pos = B_SAMPLES * T_LEN;
    softmax_conf_kernel<<<n_pos / POS_PER_CTA, K1_THREADS>>>(x);
    topk_kernel<<<B_SAMPLES, K2_THREADS>>>(out);
}